// round 2
// baseline (speedup 1.0000x reference)
#include <cuda_runtime.h>

#define NANG  4
#define NELEM 128
#define NZ    192
#define NX    192
#define NSAMP 2048
#define NPIX  (NZ * NX)

#define PI_F      3.14159265359f
#define HALF_PI_F 1.57079632679f
#define FS_F      20832000.0f
#define C_F       1540.0f
#define FDEMOD_F  5208000.0f
#define FSoC      (FS_F / C_F)
#define MINW_F    0.001f
#define FNUM_F    2.0f

// Scratch (static device globals -- no allocation)
__device__ float2 g_iq[NANG * NELEM * NSAMP];   // interleaved (i,q) per sample, 8 MB
__device__ float  g_acc[NANG * 2][NPIX];        // per-angle partial sums (i,q)

// ---------------------------------------------------------------------------
// Pass 1: interleave idata/qdata into float2 so each lerp endpoint is 1 LDG.64
// ---------------------------------------------------------------------------
__global__ void interleave_k(const float* __restrict__ id,
                             const float* __restrict__ qd) {
    int i = blockIdx.x * blockDim.x + threadIdx.x;
    if (i < NANG * NELEM * NSAMP)
        g_iq[i] = make_float2(id[i], qd[i]);
}

// ---------------------------------------------------------------------------
// Pass 2: main DAS kernel. One thread per pixel, one block-z per angle.
// Accumulates complex sum with the exact (pi/2)*delays rotation; the
// pixel-constant -4*pi*FDEMOD*z/C rotation is deferred to the reduce pass.
// ---------------------------------------------------------------------------
__global__ __launch_bounds__(256)
void das_k(const float* __restrict__ grid,
           const float* __restrict__ angles,
           const float* __restrict__ ele,
           const float* __restrict__ tz) {
    __shared__ float sex[NELEM];
    int t = threadIdx.x;                     // 0..255, tile = 32(x) x 8(z)
    if (t < NELEM) sex[t] = ele[t * 3];      // ele_pos[e,0]
    __syncthreads();

    const int a  = blockIdx.z;
    const int ix = blockIdx.x * 32 + (t & 31);
    const int iz = blockIdx.y * 8  + (t >> 5);
    const int p  = iz * NX + ix;

    const float x = grid[3 * p + 0];
    const float z = grid[3 * p + 2];

    const float ang = angles[a];
    const float sa = sinf(ang);
    const float ca = cosf(ang);
    const float ta = tanf(ang);

    const float txdel = (x * sa + z * ca + tz[a] * C_F) * FSoC;

    const float ex0 = sex[0];
    const float exN = sex[NELEM - 1];

    // tx apodization
    const float xproj = x - z * ta;
    const bool txapo = (xproj >= ex0 * 1.2f) && (xproj <= exN * 1.2f);

    float ai = 0.0f, aq = 0.0f;

    if (txapo) {
        const float zz = z * z;
        const float2* __restrict__ base = g_iq + (size_t)a * NELEM * NSAMP;

        #pragma unroll 4
        for (int e = 0; e < NELEM; e++) {
            const float ex  = sex[e];
            const float vx  = x - ex;
            const float avx = fabsf(vx);
            // rx apodization (vz = z > 0 always): |z/vx| > FNUM  <=>  z > 2|vx|
            bool keep = (z > FNUM_F * avx) || (avx <= MINW_F)
                      || ((vx >=  MINW_F) && (x <= ex0))
                      || ((vx <= -MINW_F) && (x >= exN));
            if (keep) {
                const float rxdel = sqrtf(fmaf(vx, vx, zz)) * FSoC;
                const float delay = txdel + rxdel;
                const float i0f   = floorf(delay);
                const float frac  = delay - i0f;
                const int   i0    = (int)i0f;

                const float2* __restrict__ row = base + (e * NSAMP);
                float2 p0 = make_float2(0.0f, 0.0f);
                float2 p1 = make_float2(0.0f, 0.0f);
                if ((unsigned)i0 < (unsigned)NSAMP)       p0 = row[i0];
                if ((unsigned)(i0 + 1) < (unsigned)NSAMP) p1 = row[i0 + 1];

                const float ifoc = fmaf(frac, p1.x - p0.x, p0.x);
                const float qfoc = fmaf(frac, p1.y - p0.y, p0.y);

                // rotation by (pi/2)*(i0 + frac): quadrant from i0&3 (exact),
                // small-angle sincos on frac in [0,1)
                const float targ = frac * HALF_PI_F;
                const float s0 = __sinf(targ);
                const float c0 = __cosf(targ);
                const int   q  = i0 & 3;
                float ct = (q & 1) ? s0 : c0;
                float st = (q & 1) ? c0 : s0;
                const unsigned negc = (unsigned)((q + 1) & 2) << 30; // q in {1,2}
                const unsigned negs = (unsigned)(q & 2) << 30;       // q in {2,3}
                ct = __int_as_float(__float_as_int(ct) ^ negc);
                st = __int_as_float(__float_as_int(st) ^ negs);

                ai += ifoc * ct - qfoc * st;
                aq += qfoc * ct + ifoc * st;
            }
        }
    }

    g_acc[a * 2 + 0][p] = ai;
    g_acc[a * 2 + 1][p] = aq;
}

// ---------------------------------------------------------------------------
// Pass 3: sum the 4 angle partials and apply the deferred pixel-constant
// rotation phi(z) = -4*pi*FDEMOD*z/C. Uses accurate sincosf (large argument).
// ---------------------------------------------------------------------------
__global__ void reduce_k(const float* __restrict__ grid,
                         float* __restrict__ out) {
    int p = blockIdx.x * blockDim.x + threadIdx.x;
    if (p >= NPIX) return;
    float ai = g_acc[0][p] + g_acc[2][p] + g_acc[4][p] + g_acc[6][p];
    float aq = g_acc[1][p] + g_acc[3][p] + g_acc[5][p] + g_acc[7][p];
    const float z = grid[3 * p + 2];
    const float phi = (-4.0f * PI_F * FDEMOD_F / C_F) * z;
    float sb, cb;
    sincosf(phi, &sb, &cb);
    out[p]        = ai * cb - aq * sb;   // idas
    out[NPIX + p] = aq * cb + ai * sb;   // qdas
}

extern "C" void kernel_launch(void* const* d_in, const int* in_sizes, int n_in,
                              void* d_out, int out_size) {
    const float* idata  = (const float*)d_in[0];
    const float* qdata  = (const float*)d_in[1];
    const float* grid   = (const float*)d_in[2];
    const float* angles = (const float*)d_in[3];
    const float* ele    = (const float*)d_in[4];
    const float* tz     = (const float*)d_in[5];

    int total = NANG * NELEM * NSAMP;
    interleave_k<<<(total + 255) / 256, 256>>>(idata, qdata);

    dim3 g(NX / 32, NZ / 8, NANG);
    das_k<<<g, 256>>>(grid, angles, ele, tz);

    reduce_k<<<(NPIX + 255) / 256, 256>>>(grid, (float*)d_out);
}